// round 1
// baseline (speedup 1.0000x reference)
#include <cuda_runtime.h>
#include <cuda_bf16.h>
#include <math.h>

#define N_GAUSS 2048
#define HEIGHT  192
#define WIDTH   192
#define HW      (HEIGHT*WIDTH)
#define ALPHA_MAX 0.999f
#define ALPHA_MIN (1.0f/255.0f)
#define CHUNK   256

// Sorted, gathered gaussian data (depth order)
__device__ float4 g_A[N_GAUSS];  // mx, my, conic_a, conic_b
__device__ float4 g_B[N_GAUSS];  // conic_c, opacity, col_r, col_g
__device__ float2 g_C[N_GAUSS];  // col_b, sigma_threshold = log(255*op)+margin

// ---------------------------------------------------------------------------
// Kernel 1: single-block bitonic sort by depth, then gather params in order.
// ---------------------------------------------------------------------------
__global__ void sort_gather_kernel(const float* __restrict__ means2d,
                                   const float* __restrict__ conics,
                                   const float* __restrict__ colors,
                                   const float* __restrict__ opacities,
                                   const float* __restrict__ depths)
{
    __shared__ unsigned long long key[N_GAUSS];
    const int t = threadIdx.x;  // 1024 threads

    // Depths are strictly positive floats -> their bit patterns order
    // identically as unsigned ints. Pack (depth_bits << 32) | index.
    #pragma unroll
    for (int i = t; i < N_GAUSS; i += 1024) {
        unsigned db = __float_as_uint(depths[i]);
        key[i] = (((unsigned long long)db) << 32) | (unsigned)i;
    }

    // Bitonic sort, ascending. 1024 threads, one compare-swap each per phase.
    for (int k = 2; k <= N_GAUSS; k <<= 1) {
        for (int j = k >> 1; j > 0; j >>= 1) {
            __syncthreads();
            int i = ((t & ~(j - 1)) << 1) | (t & (j - 1));
            int p = i + j;
            bool asc = ((i & k) == 0);
            unsigned long long a = key[i];
            unsigned long long b = key[p];
            if ((a > b) == asc) { key[i] = b; key[p] = a; }
        }
    }
    __syncthreads();

    // Gather into depth-sorted SoA device arrays.
    #pragma unroll
    for (int s = t; s < N_GAUSS; s += 1024) {
        int src = (int)(key[s] & 0xffffffffu);
        float mx = means2d[2*src + 0];
        float my = means2d[2*src + 1];
        float ca = conics[3*src + 0];
        float cb = conics[3*src + 1];
        float cc = conics[3*src + 2];
        float op = opacities[src];
        float cr = colors[3*src + 0];
        float cg = colors[3*src + 1];
        float cbl= colors[3*src + 2];
        g_A[s] = make_float4(mx, my, ca, cb);
        g_B[s] = make_float4(cc, op, cr, cg);
        // sigma threshold: alpha = op*exp(-sigma) >= 1/255  <=>  sigma <= log(255*op).
        // +1e-4 margin so the cheap test never excludes a gaussian the exact
        // in-branch check would have kept.
        g_C[s] = make_float2(cbl, logf(255.0f * op) + 1e-4f);
    }
}

// ---------------------------------------------------------------------------
// Kernel 2: per-pixel front-to-back compositing over sorted gaussians.
// 16x16 pixel tiles (256 threads). Gaussians staged through smem in chunks;
// inner-loop smem reads are whole-warp broadcasts (conflict-free).
// ---------------------------------------------------------------------------
__global__ void __launch_bounds__(256, 4)
render_kernel(const float* __restrict__ background, float* __restrict__ out)
{
    __shared__ float4 sA[CHUNK];
    __shared__ float4 sB[CHUNK];
    __shared__ float2 sC[CHUNK];

    const int tid = threadIdx.x;
    const int x = blockIdx.x * 16 + (tid & 15);
    const int y = blockIdx.y * 16 + (tid >> 4);
    const float px = (float)x + 0.5f;
    const float py = (float)y + 0.5f;

    float T = 1.0f;
    float accr = 0.0f, accg = 0.0f, accb = 0.0f;
    bool done = false;

    for (int base = 0; base < N_GAUSS; base += CHUNK) {
        // Cooperative stage of this chunk.
        sA[tid] = g_A[base + tid];
        sB[tid] = g_B[base + tid];
        sC[tid] = g_C[base + tid];
        __syncthreads();

        if (!done) {
            #pragma unroll 4
            for (int i = 0; i < CHUNK; ++i) {
                float4 A = sA[i];
                float dx = px - A.x;
                float dy = py - A.y;
                float4 B = sB[i];
                float2 C = sC[i];
                float sigma = 0.5f * (A.z * dx * dx + B.x * dy * dy) + A.w * dx * dy;
                // Cheap reject: only a few % of gaussian-pixel pairs survive,
                // and the survivors are spatially clustered so whole warps
                // usually skip the MUFU/compositing path together.
                if (sigma > 0.0f && sigma < C.y) {
                    float alpha = fminf(ALPHA_MAX, B.y * __expf(-sigma));
                    if (alpha >= ALPHA_MIN) {  // exact reference condition
                        float w = T * alpha;
                        accr = fmaf(w, B.z, accr);
                        accg = fmaf(w, B.w, accg);
                        accb = fmaf(w, C.x, accb);
                        T *= (1.0f - alpha);
                    }
                }
            }
            // Remaining contributions are bounded by T; drop when negligible.
            done = (T < 1e-7f);
        }
        // Full barrier (protects smem reuse) + uniform early exit.
        if (__syncthreads_and((int)done)) break;
    }

    const int pix = y * WIDTH + x;
    out[0 * HW + pix] = fmaf(background[0], T, accr);
    out[1 * HW + pix] = fmaf(background[1], T, accg);
    out[2 * HW + pix] = fmaf(background[2], T, accb);
}

// ---------------------------------------------------------------------------
extern "C" void kernel_launch(void* const* d_in, const int* in_sizes, int n_in,
                              void* d_out, int out_size)
{
    const float* means2d   = (const float*)d_in[0];
    const float* conics    = (const float*)d_in[1];
    const float* colors    = (const float*)d_in[2];
    const float* opacities = (const float*)d_in[3];
    const float* depths    = (const float*)d_in[4];
    const float* background= (const float*)d_in[5];
    float* out = (float*)d_out;

    sort_gather_kernel<<<1, 1024>>>(means2d, conics, colors, opacities, depths);
    dim3 grid(WIDTH / 16, HEIGHT / 16);
    render_kernel<<<grid, 256>>>(background, out);
}

// round 2
// speedup vs baseline: 2.8542x; 2.8542x over previous
#include <cuda_runtime.h>
#include <cuda_bf16.h>
#include <math.h>

#define N_GAUSS 2048
#define HEIGHT  192
#define WIDTH   192
#define HW      (HEIGHT*WIDTH)
#define ALPHA_MAX 0.999f
#define ALPHA_MIN (1.0f/255.0f)
#define CHUNK   256

// Depth-sorted gaussian data
__device__ float4 g_A[N_GAUSS];  // mx, my, conic_a, conic_b
__device__ float4 g_B[N_GAUSS];  // conic_c, opacity, col_r, col_g
__device__ float2 g_C[N_GAUSS];  // col_b, sigma_threshold = log(255*op)+margin
__device__ float2 g_D[N_GAUSS];  // rx, ry : conservative AABB half-extents

// ---------------------------------------------------------------------------
// Kernel 1: rank-by-counting sort (keys unique) fused with param scatter.
// 32 blocks x 256 threads. Block handles 64 gaussians; 4 slice-threads per
// gaussian each count 512 keys, partial counts summed, then 64 threads
// scatter params (+ derived AABB extents) to their rank position.
// ---------------------------------------------------------------------------
__global__ void __launch_bounds__(256)
sort_scatter_kernel(const float* __restrict__ means2d,
                    const float* __restrict__ conics,
                    const float* __restrict__ colors,
                    const float* __restrict__ opacities,
                    const float* __restrict__ depths)
{
    __shared__ unsigned long long keys[N_GAUSS];
    __shared__ int cnt[4][64];
    const int tid = threadIdx.x;

    // Stage all keys: (depth_bits << 32) | index. Depths > 0 so float bit
    // pattern orders identically to the float value; index makes keys unique.
    #pragma unroll
    for (int i = tid; i < N_GAUSS; i += 256)
        keys[i] = (((unsigned long long)__float_as_uint(depths[i])) << 32) | (unsigned)i;
    __syncthreads();

    const int gl    = tid & 63;       // gaussian-within-block
    const int slice = tid >> 6;       // 0..3
    const unsigned long long mykey = keys[blockIdx.x * 64 + gl];

    int c = 0;
    const int s0 = slice * (N_GAUSS / 4);
    #pragma unroll 8
    for (int i = 0; i < N_GAUSS / 4; ++i)
        c += (keys[s0 + i] < mykey);
    cnt[slice][gl] = c;
    __syncthreads();

    if (tid < 64) {
        int rank = cnt[0][tid] + cnt[1][tid] + cnt[2][tid] + cnt[3][tid];
        int src  = blockIdx.x * 64 + tid;
        float mx = means2d[2*src + 0];
        float my = means2d[2*src + 1];
        float ca = conics[3*src + 0];
        float cb = conics[3*src + 1];
        float cc = conics[3*src + 2];
        float op = opacities[src];
        float cr = colors[3*src + 0];
        float cg = colors[3*src + 1];
        float cbl= colors[3*src + 2];
        // alpha >= 1/255  <=>  sigma <= log(255*op); +margin so the cheap
        // reject never drops a gaussian the exact in-branch check keeps.
        float t = logf(255.0f * op) + 1e-4f;
        // Support ellipse sigma<=t has AABB half-extents:
        //   rx = sqrt(2t * Qinv_xx) = sqrt(2t*cc/det), ry = sqrt(2t*ca/det)
        float det = ca * cc - cb * cb;
        float inv = 2.0f * fmaxf(t, 0.0f) / det;
        float rx = sqrtf(fmaxf(inv * cc, 0.0f)) + 1e-3f;
        float ry = sqrtf(fmaxf(inv * ca, 0.0f)) + 1e-3f;
        g_A[rank] = make_float4(mx, my, ca, cb);
        g_B[rank] = make_float4(cc, op, cr, cg);
        g_C[rank] = make_float2(cbl, t);
        g_D[rank] = make_float2(rx, ry);
    }
}

// ---------------------------------------------------------------------------
// Kernel 2: tile-culled front-to-back compositing. 16x16 pixel tiles.
// Per 256-gaussian chunk: stage to smem, each thread tests one gaussian's
// AABB against the tile, order-preserving ballot compaction, then the
// per-pixel loop runs only over survivors.
// ---------------------------------------------------------------------------
__global__ void __launch_bounds__(256, 4)
render_kernel(const float* __restrict__ background, float* __restrict__ out)
{
    __shared__ float4 sA[CHUNK];
    __shared__ float4 sB[CHUNK];
    __shared__ float2 sC[CHUNK];
    __shared__ short  sIdx[CHUNK];
    __shared__ int    warpCnt[8], warpOff[8], sCount;

    const int tid = threadIdx.x;
    const int warp = tid >> 5, lane = tid & 31;
    const int x = blockIdx.x * 16 + (tid & 15);
    const int y = blockIdx.y * 16 + (tid >> 4);
    const float px = (float)x + 0.5f;
    const float py = (float)y + 0.5f;

    // Tile pixel-center bounds
    const float txmin = blockIdx.x * 16 + 0.5f;
    const float txmax = blockIdx.x * 16 + 15.5f;
    const float tymin = blockIdx.y * 16 + 0.5f;
    const float tymax = blockIdx.y * 16 + 15.5f;

    float T = 1.0f;
    float accr = 0.0f, accg = 0.0f, accb = 0.0f;
    bool done = false;

    for (int base = 0; base < N_GAUSS; base += CHUNK) {
        // Stage + tile-intersection test (one gaussian per thread).
        float4 A = g_A[base + tid];
        float2 R = g_D[base + tid];
        sA[tid] = A;
        sB[tid] = g_B[base + tid];
        sC[tid] = g_C[base + tid];
        bool pred = (A.x - R.x <= txmax) & (A.x + R.x >= txmin) &
                    (A.y - R.y <= tymax) & (A.y + R.y >= tymin);

        // Order-preserving compaction of surviving chunk slots.
        unsigned m = __ballot_sync(0xffffffffu, pred);
        if (lane == 0) warpCnt[warp] = __popc(m);
        __syncthreads();
        if (tid == 0) {
            int acc = 0;
            #pragma unroll
            for (int w = 0; w < 8; ++w) { warpOff[w] = acc; acc += warpCnt[w]; }
            sCount = acc;
        }
        __syncthreads();
        if (pred)
            sIdx[warpOff[warp] + __popc(m & ((1u << lane) - 1u))] = (short)tid;
        __syncthreads();

        const int nSel = sCount;
        if (!done) {
            for (int i = 0; i < nSel; ++i) {
                int j = sIdx[i];                 // broadcast, conflict-free
                float4 a = sA[j];
                float dx = px - a.x;
                float dy = py - a.y;
                float4 b = sB[j];
                float2 cpk = sC[j];
                float sigma = 0.5f * (a.z * dx * dx + b.x * dy * dy) + a.w * dx * dy;
                if (sigma > 0.0f && sigma < cpk.y) {
                    float alpha = fminf(ALPHA_MAX, b.y * __expf(-sigma));
                    if (alpha >= ALPHA_MIN) {    // exact reference condition
                        float w = T * alpha;
                        accr = fmaf(w, b.z, accr);
                        accg = fmaf(w, b.w, accg);
                        accb = fmaf(w, cpk.x, accb);
                        T *= (1.0f - alpha);
                    }
                }
            }
            done = (T < 1e-7f);   // remaining contributions bounded by T
        }
        if (__syncthreads_and((int)done)) break;
    }

    const int pix = y * WIDTH + x;
    out[0 * HW + pix] = fmaf(background[0], T, accr);
    out[1 * HW + pix] = fmaf(background[1], T, accg);
    out[2 * HW + pix] = fmaf(background[2], T, accb);
}

// ---------------------------------------------------------------------------
extern "C" void kernel_launch(void* const* d_in, const int* in_sizes, int n_in,
                              void* d_out, int out_size)
{
    const float* means2d    = (const float*)d_in[0];
    const float* conics     = (const float*)d_in[1];
    const float* colors     = (const float*)d_in[2];
    const float* opacities  = (const float*)d_in[3];
    const float* depths     = (const float*)d_in[4];
    const float* background = (const float*)d_in[5];
    float* out = (float*)d_out;

    sort_scatter_kernel<<<32, 256>>>(means2d, conics, colors, opacities, depths);
    dim3 grid(WIDTH / 16, HEIGHT / 16);
    render_kernel<<<grid, 256>>>(background, out);
}

// round 3
// speedup vs baseline: 4.0191x; 1.4082x over previous
#include <cuda_runtime.h>
#include <cuda_bf16.h>
#include <math.h>

#define N_GAUSS 2048
#define HEIGHT  192
#define WIDTH   192
#define HW      (HEIGHT*WIDTH)
#define ALPHA_MAX 0.999f
#define ALPHA_MIN (1.0f/255.0f)
#define CHUNK   1024

// Depth-sorted gaussian data
__device__ float4 g_A[N_GAUSS];  // mx, my, conic_a, conic_b
__device__ float4 g_B[N_GAUSS];  // conic_c, opacity, col_r, col_g
__device__ float2 g_C[N_GAUSS];  // col_b, sigma_threshold = log(255*op)+margin
__device__ float2 g_D[N_GAUSS];  // rx, ry : conservative AABB half-extents

// ---------------------------------------------------------------------------
// Kernel 1: rank-by-counting sort (keys unique) fused with param scatter.
// 128 blocks x 256 threads. Block handles 16 gaussians; 16 slice-threads per
// gaussian each count 128 keys; ranks summed; 16 threads scatter params.
// ---------------------------------------------------------------------------
__global__ void __launch_bounds__(256)
sort_scatter_kernel(const float* __restrict__ means2d,
                    const float* __restrict__ conics,
                    const float* __restrict__ colors,
                    const float* __restrict__ opacities,
                    const float* __restrict__ depths)
{
    __shared__ unsigned long long keys[N_GAUSS];
    __shared__ int cnt[16][17];          // padded vs bank conflicts
    const int tid = threadIdx.x;

    // (depth_bits << 32) | index : depths > 0 so float bits order like floats;
    // index makes keys unique.
    #pragma unroll
    for (int i = tid; i < N_GAUSS; i += 256)
        keys[i] = (((unsigned long long)__float_as_uint(depths[i])) << 32) | (unsigned)i;
    __syncthreads();

    const int gl    = tid & 15;          // gaussian-within-block
    const int slice = tid >> 4;          // 0..15
    const unsigned long long mykey = keys[blockIdx.x * 16 + gl];

    int c = 0;
    const int s0 = slice * (N_GAUSS / 16);
    #pragma unroll 8
    for (int i = 0; i < N_GAUSS / 16; ++i)
        c += (keys[s0 + i] < mykey);
    cnt[slice][gl] = c;
    __syncthreads();

    if (tid < 16) {
        int rank = 0;
        #pragma unroll
        for (int s = 0; s < 16; ++s) rank += cnt[s][tid];
        int src = blockIdx.x * 16 + tid;
        float mx = means2d[2*src + 0];
        float my = means2d[2*src + 1];
        float ca = conics[3*src + 0];
        float cb = conics[3*src + 1];
        float cc = conics[3*src + 2];
        float op = opacities[src];
        float cr = colors[3*src + 0];
        float cg = colors[3*src + 1];
        float cbl= colors[3*src + 2];
        // alpha >= 1/255  <=>  sigma <= log(255*op); +margin so the cheap
        // reject never drops a gaussian the exact in-branch check keeps.
        float t = logf(255.0f * op) + 1e-4f;
        // Support ellipse sigma<=t AABB half-extents:
        //   rx = sqrt(2t*cc/det), ry = sqrt(2t*ca/det)
        float det = ca * cc - cb * cb;
        float inv = 2.0f * fmaxf(t, 0.0f) / det;
        float rx = sqrtf(fmaxf(inv * cc, 0.0f)) + 1e-3f;
        float ry = sqrtf(fmaxf(inv * ca, 0.0f)) + 1e-3f;
        g_A[rank] = make_float4(mx, my, ca, cb);
        g_B[rank] = make_float4(cc, op, cr, cg);
        g_C[rank] = make_float2(cbl, t);
        g_D[rank] = make_float2(rx, ry);
    }
}

// ---------------------------------------------------------------------------
// Kernel 2: per-warp strip-culled front-to-back compositing.
// 16x16 pixel tile per block (256 threads); each warp owns a 16x2 strip.
// Gaussians staged in two 1024-chunks (48KB smem). Per 32-group: lane-parallel
// AABB test vs the warp's strip -> ballot -> uniform ffs walk of survivors.
// No compaction barriers; per-warp early exit.
// ---------------------------------------------------------------------------
__global__ void __launch_bounds__(256)
render_kernel(const float* __restrict__ background, float* __restrict__ out)
{
    __shared__ float4 sA[CHUNK];
    __shared__ float4 sB[CHUNK];
    __shared__ float2 sC[CHUNK];
    __shared__ float2 sD[CHUNK];

    const int tid  = threadIdx.x;
    const int warp = tid >> 5, lane = tid & 31;
    const int x = blockIdx.x * 16 + (tid & 15);
    const int y = blockIdx.y * 16 + (tid >> 4);
    const float px = (float)x + 0.5f;
    const float py = (float)y + 0.5f;

    // This warp's 16x2 pixel-center strip bounds.
    const float sxmin = blockIdx.x * 16 + 0.5f;
    const float sxmax = blockIdx.x * 16 + 15.5f;
    const float symin = blockIdx.y * 16 + 2 * warp + 0.5f;
    const float symax = symin + 1.0f;

    float T = 1.0f;
    float accr = 0.0f, accg = 0.0f, accb = 0.0f;
    bool wdone = false;

    for (int base = 0; base < N_GAUSS; base += CHUNK) {
        if (base) __syncthreads();           // protect smem reuse
        #pragma unroll
        for (int k = 0; k < CHUNK / 256; ++k) {
            int i = tid + k * 256;
            sA[i] = g_A[base + i];
            sB[i] = g_B[base + i];
            sC[i] = g_C[base + i];
            sD[i] = g_D[base + i];
        }
        __syncthreads();

        if (!wdone) {
            for (int g = 0; g < CHUNK; g += 32) {
                // Lane-parallel cull of this 32-group against the strip.
                float4 a = sA[g + lane];
                float2 r = sD[g + lane];
                bool pred = (a.x - r.x <= sxmax) & (a.x + r.x >= sxmin) &
                            (a.y - r.y <= symax) & (a.y + r.y >= symin);
                unsigned mask = __ballot_sync(0xffffffffu, pred);

                // Uniform in-order walk over survivors (whole-warp broadcast).
                while (mask) {
                    int j = g + (__ffs(mask) - 1);
                    mask &= mask - 1;
                    float4 A = sA[j];
                    float dx = px - A.x;
                    float dy = py - A.y;
                    float4 B = sB[j];
                    float2 C = sC[j];
                    float sigma = 0.5f * (A.z * dx * dx + B.x * dy * dy) + A.w * dx * dy;
                    if (sigma > 0.0f && sigma < C.y) {
                        float alpha = fminf(ALPHA_MAX, B.y * __expf(-sigma));
                        if (alpha >= ALPHA_MIN) {   // exact reference condition
                            float w = T * alpha;
                            accr = fmaf(w, B.z, accr);
                            accg = fmaf(w, B.w, accg);
                            accb = fmaf(w, C.x, accb);
                            T *= (1.0f - alpha);
                        }
                    }
                }
                // Per-warp early exit: remaining contributions bounded by T.
                if (!__ballot_sync(0xffffffffu, T >= 1e-7f)) { wdone = true; break; }
            }
        }
    }

    const int pix = y * WIDTH + x;
    out[0 * HW + pix] = fmaf(background[0], T, accr);
    out[1 * HW + pix] = fmaf(background[1], T, accg);
    out[2 * HW + pix] = fmaf(background[2], T, accb);
}

// ---------------------------------------------------------------------------
extern "C" void kernel_launch(void* const* d_in, const int* in_sizes, int n_in,
                              void* d_out, int out_size)
{
    const float* means2d    = (const float*)d_in[0];
    const float* conics     = (const float*)d_in[1];
    const float* colors     = (const float*)d_in[2];
    const float* opacities  = (const float*)d_in[3];
    const float* depths     = (const float*)d_in[4];
    const float* background = (const float*)d_in[5];
    float* out = (float*)d_out;

    sort_scatter_kernel<<<128, 256>>>(means2d, conics, colors, opacities, depths);
    dim3 grid(WIDTH / 16, HEIGHT / 16);
    render_kernel<<<grid, 256>>>(background, out);
}